// round 8
// baseline (speedup 1.0000x reference)
#include <cuda_runtime.h>

#define HWSZ 40000
#define WD 200
#define HD 200

typedef unsigned long long u64;

__device__ __forceinline__ u64 pack2(float lo, float hi) {
    u64 r; asm("mov.b64 %0, {%1, %2};" : "=l"(r) : "f"(lo), "f"(hi)); return r;
}
__device__ __forceinline__ void ffma2(u64 &d, u64 a, u64 b) {
    asm("fma.rn.f32x2 %0, %1, %2, %0;" : "+l"(d) : "l"(a), "l"(b));
}
__device__ __forceinline__ float2 unpack2(u64 v) {
    float2 r; asm("mov.b64 {%0, %1}, %2;" : "=f"(r.x), "=f"(r.y) : "l"(v)); return r;
}

// ---- scratch (allocation-free: __device__ globals) ----
__device__ float g_e    [8 * 64  * HWSZ];
__device__ float g_e2   [8 * 64  * HWSZ];
__device__ float g_corr [4 * 81  * HWSZ];
__device__ float g_align[4 * 128 * HWSZ];

// ============================================================================
// conv1x1 (128 -> 64) + bias + relu, packed f32x2 over c-pairs.
// grid (157, 8), block 256. Block = 64 oc x 256 px; thread = 8 oc x 8 px.
// Accumulator lanes: lane0 = even c partial sum, lane1 = odd c.
// ============================================================================
__global__ __launch_bounds__(256) void conv1x1_relu_f2(
    const float* __restrict__ src0, const float* __restrict__ src1,
    const float* __restrict__ w, const float* __restrict__ bias,
    float* __restrict__ out)
{
    __shared__ __align__(16) u64 ws2[8][64];    // [cp][oc]  (w[2cp],w[2cp+1])
    __shared__ __align__(16) u64 xs2[8][256];   // [cp][px]

    const int n = blockIdx.y;
    const float* src = (n < 4) ? (src0 + (size_t)n * 128 * HWSZ)
                               : (src1 + (size_t)(n - 4) * 128 * HWSZ);
    const int px_base = blockIdx.x * 256;
    const int t = threadIdx.x;
    const int oc0 = (t >> 5) * 8;
    const int px0 = (t & 31) * 8;

    u64 acc[8][8];
    #pragma unroll
    for (int o = 0; o < 8; o++)
        #pragma unroll
        for (int p = 0; p < 8; p++) acc[o][p] = 0ull;

    for (int c0 = 0; c0 < 128; c0 += 16) {   // 8 c-pairs per stage
        __syncthreads();
        // weights: contiguous even/odd c in global -> direct u64 load
        {
            int i = t;            // 512 entries, 2 per thread
            int cp = i >> 6, oc = i & 63;
            ws2[cp][oc] = *(const u64*)(w + oc * 128 + c0 + 2 * cp);
            i += 256; cp = i >> 6; oc = i & 63;
            ws2[cp][oc] = *(const u64*)(w + oc * 128 + c0 + 2 * cp);
        }
        #pragma unroll
        for (int it = 0; it < 8; it++) {      // 2048 x entries
            int i = t + it * 256;
            int cp = i >> 8, px = i & 255;
            int gpx = px_base + px;
            u64 v = 0ull;
            if (gpx < HWSZ) {
                const float* p0 = src + (size_t)(c0 + 2 * cp) * HWSZ + gpx;
                v = pack2(p0[0], p0[HWSZ]);
            }
            xs2[cp][px] = v;
        }
        __syncthreads();

        #pragma unroll
        for (int cp = 0; cp < 8; cp++) {
            u64 wv[8], xv[8];
            #pragma unroll
            for (int i = 0; i < 4; i++) {
                ulonglong2 a = *(const ulonglong2*)&ws2[cp][oc0 + i * 2];
                wv[i * 2] = a.x; wv[i * 2 + 1] = a.y;
                ulonglong2 b = *(const ulonglong2*)&xs2[cp][px0 + i * 2];
                xv[i * 2] = b.x; xv[i * 2 + 1] = b.y;
            }
            #pragma unroll
            for (int o = 0; o < 8; o++)
                #pragma unroll
                for (int p = 0; p < 8; p++)
                    ffma2(acc[o][p], wv[o], xv[p]);
        }
    }

    if (px_base + px0 < HWSZ) {
        #pragma unroll
        for (int o = 0; o < 8; o++) {
            float b = bias[oc0 + o];
            float r[8];
            #pragma unroll
            for (int p = 0; p < 8; p++) {
                float2 l = unpack2(acc[o][p]);
                r[p] = fmaxf(l.x + l.y + b, 0.f);
            }
            float* op = out + (size_t)(n * 64 + oc0 + o) * HWSZ + px_base + px0;
            *(float4*)op       = make_float4(r[0], r[1], r[2], r[3]);
            *(float4*)(op + 4) = make_float4(r[4], r[5], r[6], r[7]);
        }
    }
}

// ============================================================================
// conv3x3 (64 -> CO) pad 1 + bias + relu, packed f32x2 over ic-pairs.
// grid (7, 13, 8*CO/32), block 256. Tile 16 rows x 32 cols x 32 oc.
// Thread = 2 rows x 4 cols x 8 oc.
// ============================================================================
__global__ __launch_bounds__(256) void conv3x3_relu_f2(
    const float* __restrict__ in, const float* __restrict__ w,
    const float* __restrict__ bias, float* __restrict__ out, int CO)
{
    __shared__ __align__(16) u64 si2[4][18][35];   // [icp][row][col] halo tile
    __shared__ __align__(16) u64 sw2[4][9][32];    // [icp][tap][oc]

    const int passes = CO >> 5;
    const int n = blockIdx.z / passes;
    const int pass = blockIdx.z - n * passes;
    const int ocbase = pass * 32;
    const int gy0 = blockIdx.y * 16, gx0 = blockIdx.x * 32;
    const int t = threadIdx.x;
    const int oc0 = (t >> 6) * 8;          // 4 oc groups
    const int pxg = t & 63;
    const int row0 = (pxg >> 3) * 2;       // 8 row groups x 2 rows
    const int col0 = (pxg & 7) * 4;        // 8 col groups x 4 cols
    const float* inb = in + (size_t)n * 64 * HWSZ;

    u64 acc[2][4][8];
    #pragma unroll
    for (int rr = 0; rr < 2; rr++)
        #pragma unroll
        for (int cc = 0; cc < 4; cc++)
            #pragma unroll
            for (int o = 0; o < 8; o++) acc[rr][cc][o] = 0ull;

    for (int ic0 = 0; ic0 < 64; ic0 += 8) {   // 4 ic-pairs per stage
        __syncthreads();
        for (int i = t; i < 4 * 18 * 34; i += 256) {
            int icp = i / 612;
            int rem = i - icp * 612;
            int r = rem / 34, cc = rem - r * 34;
            int gy = gy0 - 1 + r, gx = gx0 - 1 + cc;
            u64 v = 0ull;
            if (gy >= 0 && gy < HD && gx >= 0 && gx < WD) {
                const float* p = inb + (size_t)(ic0 + 2 * icp) * HWSZ + gy * WD + gx;
                v = pack2(p[0], p[HWSZ]);
            }
            si2[icp][r][cc] = v;
        }
        for (int i = t; i < 4 * 9 * 32; i += 256) {
            int oc = i & 31;
            int rest = i >> 5;
            int icp = rest / 9, tap = rest - icp * 9;
            const float* p = w + (size_t)((ocbase + oc) * 64 + ic0 + 2 * icp) * 9 + tap;
            sw2[icp][tap][oc] = pack2(p[0], p[9]);
        }
        __syncthreads();

        #pragma unroll
        for (int icp = 0; icp < 4; icp++) {
            #pragma unroll
            for (int ki = 0; ki < 3; ki++) {
                u64 xw[2][6];
                #pragma unroll
                for (int rr = 0; rr < 2; rr++)
                    #pragma unroll
                    for (int c = 0; c < 6; c++)
                        xw[rr][c] = si2[icp][row0 + rr + ki][col0 + c];
                #pragma unroll
                for (int kj = 0; kj < 3; kj++) {
                    u64 wv[8];
                    #pragma unroll
                    for (int i2 = 0; i2 < 4; i2++) {
                        ulonglong2 a = *(const ulonglong2*)&sw2[icp][ki * 3 + kj][oc0 + i2 * 2];
                        wv[i2 * 2] = a.x; wv[i2 * 2 + 1] = a.y;
                    }
                    #pragma unroll
                    for (int rr = 0; rr < 2; rr++)
                        #pragma unroll
                        for (int cc = 0; cc < 4; cc++)
                            #pragma unroll
                            for (int o = 0; o < 8; o++)
                                ffma2(acc[rr][cc][o], wv[o], xw[rr][cc + kj]);
                }
            }
        }
    }

    const int gx = gx0 + col0;
    #pragma unroll
    for (int rr = 0; rr < 2; rr++) {
        int gy = gy0 + row0 + rr;
        if (gy < HD && gx < WD) {
            #pragma unroll
            for (int o = 0; o < 8; o++) {
                float b = bias[ocbase + oc0 + o];
                float4 r;
                float2 l0 = unpack2(acc[rr][0][o]);
                float2 l1 = unpack2(acc[rr][1][o]);
                float2 l2 = unpack2(acc[rr][2][o]);
                float2 l3 = unpack2(acc[rr][3][o]);
                r.x = fmaxf(l0.x + l0.y + b, 0.f);
                r.y = fmaxf(l1.x + l1.y + b, 0.f);
                r.z = fmaxf(l2.x + l2.y + b, 0.f);
                r.w = fmaxf(l3.x + l3.y + b, 0.f);
                *(float4*)&out[(size_t)(n * CO + ocbase + oc0 + o) * HWSZ + gy * WD + gx] = r;
            }
        }
    }
}

// ============================================================================
// correlation, packed f32x2 over c-pairs. grid (40, 9, 4), block 256.
// ============================================================================
__global__ __launch_bounds__(256) void corr_kernel(
    const float* __restrict__ e, float* __restrict__ corr)
{
    const int n = blockIdx.z, di = blockIdx.y;
    const int q = blockIdx.x * 256 + threadIdx.x;
    if (q >= 10000) return;
    const int p0 = q * 4;
    const int y = p0 / WD, x0 = p0 - y * WD;
    const float* sel = e + (size_t)n * 64 * HWSZ;
    const float* cur = e + (size_t)(n + 4) * 64 * HWSZ;

    u64 acc[9][4];
    #pragma unroll
    for (int dj = 0; dj < 9; dj++)
        #pragma unroll
        for (int j = 0; j < 4; j++) acc[dj][j] = 0ull;

    const int yy = y + di - 4;
    if (yy >= 0 && yy < HD) {
        #pragma unroll 1
        for (int c = 0; c < 64; c += 2) {
            float4 s0 = *(const float4*)&sel[(size_t)c * HWSZ + p0];
            float4 s1 = *(const float4*)&sel[(size_t)(c + 1) * HWSZ + p0];
            u64 sp[4];
            sp[0] = pack2(s0.x, s1.x); sp[1] = pack2(s0.y, s1.y);
            sp[2] = pack2(s0.z, s1.z); sp[3] = pack2(s0.w, s1.w);
            const float* r0 = &cur[(size_t)c * HWSZ + yy * WD];
            u64 wp[12];
            #pragma unroll
            for (int i = 0; i < 12; i++) {
                int xx = x0 - 4 + i;
                wp[i] = (xx >= 0 && xx < WD) ? pack2(r0[xx], r0[xx + HWSZ]) : 0ull;
            }
            #pragma unroll
            for (int dj = 0; dj < 9; dj++)
                #pragma unroll
                for (int j = 0; j < 4; j++)
                    ffma2(acc[dj][j], sp[j], wp[dj + j]);
        }
    }
    #pragma unroll
    for (int dj = 0; dj < 9; dj++) {
        float4 r;
        float2 a0 = unpack2(acc[dj][0]); float2 a1 = unpack2(acc[dj][1]);
        float2 a2 = unpack2(acc[dj][2]); float2 a3 = unpack2(acc[dj][3]);
        r.x = a0.x + a0.y; r.y = a1.x + a1.y; r.z = a2.x + a2.y; r.w = a3.x + a3.y;
        *(float4*)&corr[(size_t)(n * 81 + di * 9 + dj) * HWSZ + p0] = r;
    }
}

// ============================================================================
// softmax over k=81, online max+sum pass then normalize. grid 157, block 256.
// ============================================================================
__global__ __launch_bounds__(256) void softmax81(float* __restrict__ c)
{
    const int tid = blockIdx.x * 256 + threadIdx.x;
    if (tid >= 40000) return;
    const int n = tid / 10000, q = tid - n * 10000;
    float* base = c + (size_t)n * 81 * HWSZ + q * 4;

    float4 m = {-1e30f, -1e30f, -1e30f, -1e30f};
    float4 s = {0.f, 0.f, 0.f, 0.f};
    for (int k = 0; k < 81; k++) {
        float4 v = *(const float4*)(base + (size_t)k * HWSZ);
        float4 nm;
        nm.x = fmaxf(m.x, v.x); nm.y = fmaxf(m.y, v.y);
        nm.z = fmaxf(m.z, v.z); nm.w = fmaxf(m.w, v.w);
        s.x = s.x * __expf(m.x - nm.x) + __expf(v.x - nm.x);
        s.y = s.y * __expf(m.y - nm.y) + __expf(v.y - nm.y);
        s.z = s.z * __expf(m.z - nm.z) + __expf(v.z - nm.z);
        s.w = s.w * __expf(m.w - nm.w) + __expf(v.w - nm.w);
        m = nm;
    }
    float4 inv = {1.f / s.x, 1.f / s.y, 1.f / s.z, 1.f / s.w};
    for (int k = 0; k < 81; k++) {
        float* p = base + (size_t)k * HWSZ;
        float4 v = *(const float4*)p;
        float4 r;
        r.x = __expf(v.x - m.x) * inv.x;
        r.y = __expf(v.y - m.y) * inv.y;
        r.z = __expf(v.z - m.z) * inv.z;
        r.w = __expf(v.w - m.w) * inv.w;
        *(float4*)p = r;
    }
}

// ============================================================================
// align[n][c][p] = sum_k w[n][k][p] * sel[n][c][p + off_k]
// grid (157, 4 cpass, 4 n), block 256 = 64 quads x 4 c-groups (8c each).
// ============================================================================
__global__ __launch_bounds__(256) void align_kernel(
    const float* __restrict__ wgt, const float* __restrict__ fsel,
    float* __restrict__ outp)
{
    __shared__ __align__(16) float ws[9 * 256];

    const int n = blockIdx.z, cpass = blockIdx.y;
    const int t = threadIdx.x;
    const int ql = t & 63, cg = t >> 6;
    const int qb = blockIdx.x * 64;
    const int q = qb + ql;
    const bool active = q < 10000;
    const int p0 = q * 4;
    const int y = p0 / WD, x0 = p0 - y * WD;
    const int c0 = cpass * 32 + cg * 8;
    const float* sel = fsel + (size_t)n * 128 * HWSZ;
    const int pxbase = qb * 4;

    float acc[8][4];
    #pragma unroll
    for (int ci = 0; ci < 8; ci++)
        #pragma unroll
        for (int j = 0; j < 4; j++) acc[ci][j] = 0.f;

    for (int di = 0; di < 9; di++) {
        __syncthreads();
        #pragma unroll
        for (int i2 = 0; i2 < 9; i2++) {
            int i = t + i2 * 256;
            int dj = i >> 8, col = i & 255;
            int idx = pxbase + col;
            ws[i] = (idx < HWSZ) ? wgt[(size_t)(n * 81 + di * 9 + dj) * HWSZ + idx] : 0.f;
        }
        __syncthreads();

        const int yy = y + di - 4;
        if (active && yy >= 0 && yy < HD) {
            float4 wv[9];
            #pragma unroll
            for (int dj = 0; dj < 9; dj++)
                wv[dj] = *(const float4*)&ws[dj * 256 + ql * 4];
            #pragma unroll
            for (int ci = 0; ci < 8; ci++) {
                const float* srow = sel + (size_t)(c0 + ci) * HWSZ + yy * WD;
                float win[12];
                #pragma unroll
                for (int i2 = 0; i2 < 12; i2++) {
                    int xx = x0 - 4 + i2;
                    win[i2] = (xx >= 0 && xx < WD) ? srow[xx] : 0.f;
                }
                #pragma unroll
                for (int dj = 0; dj < 9; dj++) {
                    acc[ci][0] += wv[dj].x * win[dj];
                    acc[ci][1] += wv[dj].y * win[dj + 1];
                    acc[ci][2] += wv[dj].z * win[dj + 2];
                    acc[ci][3] += wv[dj].w * win[dj + 3];
                }
            }
        }
    }

    if (active) {
        #pragma unroll
        for (int ci = 0; ci < 8; ci++) {
            float4 r = {acc[ci][0], acc[ci][1], acc[ci][2], acc[ci][3]};
            *(float4*)&outp[(size_t)(n * 128 + c0 + ci) * HWSZ + p0] = r;
        }
    }
}

// ============================================================================
// ag3 1x1 (32->1) + relu, 2-way softmax, final blend.
// ============================================================================
__global__ __launch_bounds__(256) void final_blend(
    const float* __restrict__ a2, const float* __restrict__ alg,
    const float* __restrict__ fcur, const float* __restrict__ w3,
    const float* __restrict__ b3, float* __restrict__ out)
{
    const int tid = blockIdx.x * 256 + threadIdx.x;
    if (tid >= 40000) return;
    const int n = tid / 10000, q = tid - n * 10000;
    const int p0 = q * 4;

    float4 z0 = {0.f, 0.f, 0.f, 0.f}, z1 = {0.f, 0.f, 0.f, 0.f};
    #pragma unroll 4
    for (int c = 0; c < 32; c++) {
        float wc = w3[c];
        float4 va = *(const float4*)&a2[(size_t)(n * 32 + c) * HWSZ + p0];
        float4 vb = *(const float4*)&a2[(size_t)((n + 4) * 32 + c) * HWSZ + p0];
        z0.x += wc * va.x; z0.y += wc * va.y; z0.z += wc * va.z; z0.w += wc * va.w;
        z1.x += wc * vb.x; z1.y += wc * vb.y; z1.z += wc * vb.z; z1.w += wc * vb.w;
    }
    const float b = b3[0];
    z0.x = fmaxf(z0.x + b, 0.f); z0.y = fmaxf(z0.y + b, 0.f);
    z0.z = fmaxf(z0.z + b, 0.f); z0.w = fmaxf(z0.w + b, 0.f);
    z1.x = fmaxf(z1.x + b, 0.f); z1.y = fmaxf(z1.y + b, 0.f);
    z1.z = fmaxf(z1.z + b, 0.f); z1.w = fmaxf(z1.w + b, 0.f);

    float4 w0;
    w0.x = 1.f / (1.f + __expf(z1.x - z0.x));
    w0.y = 1.f / (1.f + __expf(z1.y - z0.y));
    w0.z = 1.f / (1.f + __expf(z1.z - z0.z));
    w0.w = 1.f / (1.f + __expf(z1.w - z0.w));

    #pragma unroll 4
    for (int c = 0; c < 128; c++) {
        float4 va = *(const float4*)&alg[(size_t)(n * 128 + c) * HWSZ + p0];
        float4 vc = *(const float4*)&fcur[(size_t)(n * 128 + c) * HWSZ + p0];
        float4 r;
        r.x = w0.x * va.x + (1.f - w0.x) * vc.x;
        r.y = w0.y * va.y + (1.f - w0.y) * vc.y;
        r.z = w0.z * va.z + (1.f - w0.z) * vc.z;
        r.w = w0.w * va.w + (1.f - w0.w) * vc.w;
        *(float4*)&out[(size_t)(n * 128 + c) * HWSZ + p0] = r;
    }
}

// ============================================================================
extern "C" void kernel_launch(void* const* d_in, const int* in_sizes, int n_in,
                              void* d_out, int out_size)
{
    (void)in_sizes; (void)n_in; (void)out_size;
    const float* fsel  = (const float*)d_in[0];
    const float* fcur  = (const float*)d_in[1];
    const float* ec1_w = (const float*)d_in[2];
    const float* ec1_b = (const float*)d_in[3];
    const float* ec2_w = (const float*)d_in[4];
    const float* ec2_b = (const float*)d_in[5];
    const float* ag1_w = (const float*)d_in[6];
    const float* ag1_b = (const float*)d_in[7];
    const float* ag2_w = (const float*)d_in[8];
    const float* ag2_b = (const float*)d_in[9];
    const float* ag3_w = (const float*)d_in[10];
    const float* ag3_b = (const float*)d_in[11];
    float* out = (float*)d_out;

    float *pe, *pe2, *pcorr, *palign;
    cudaGetSymbolAddress((void**)&pe,     g_e);
    cudaGetSymbolAddress((void**)&pe2,    g_e2);
    cudaGetSymbolAddress((void**)&pcorr,  g_corr);
    cudaGetSymbolAddress((void**)&palign, g_align);

    conv1x1_relu_f2<<<dim3(157, 8), 256>>>(fsel, fcur, ec1_w, ec1_b, pe);
    conv3x3_relu_f2<<<dim3(7, 13, 16), 256>>>(pe, ec2_w, ec2_b, pe2, 64);
    corr_kernel<<<dim3(40, 9, 4), 256>>>(pe2, pcorr);
    softmax81<<<157, 256>>>(pcorr);
    align_kernel<<<dim3(157, 4, 4), 256>>>(pcorr, fsel, palign);
    conv1x1_relu_f2<<<dim3(157, 8), 256>>>(palign, fcur, ag1_w, ag1_b, pe);
    conv3x3_relu_f2<<<dim3(7, 13, 8), 256>>>(pe, ag2_w, ag2_b, pe2, 32);
    final_blend<<<157, 256>>>(pe2, palign, fcur, ag3_w, ag3_b, out);
}

// round 13
// speedup vs baseline: 1.1590x; 1.1590x over previous
#include <cuda_runtime.h>
#include <cstdint>

#define HWSZ 40000
#define WD 200
#define HD 200

typedef unsigned long long u64;

__device__ __forceinline__ u64 pack2(float lo, float hi) {
    u64 r; asm("mov.b64 %0, {%1, %2};" : "=l"(r) : "f"(lo), "f"(hi)); return r;
}
__device__ __forceinline__ void ffma2(u64 &d, u64 a, u64 b) {
    asm("fma.rn.f32x2 %0, %1, %2, %0;" : "+l"(d) : "l"(a), "l"(b));
}
__device__ __forceinline__ float2 unpack2(u64 v) {
    float2 r; asm("mov.b64 {%0, %1}, %2;" : "=f"(r.x), "=f"(r.y) : "l"(v)); return r;
}

// ---- scratch (allocation-free: __device__ globals) ----
__device__ float g_e    [8 * 64  * HWSZ];
__device__ float g_e2   [8 * 64  * HWSZ];
__device__ float g_corr [4 * 81  * HWSZ];
__device__ float g_align[4 * 128 * HWSZ];

// ============================================================================
// conv1x1 (128 -> 64) + bias + relu, f32x2 over c-pairs, LEAN registers.
// grid (313, 8), block 256 = 8 ocgroups x 32 px-slots. Tile 64oc x 128px.
// thread = 8 oc x 4 px; acc = 32 u64. Warp-uniform ocg -> weight broadcast.
// ============================================================================
__global__ __launch_bounds__(256) void conv1x1_f2(
    const float* __restrict__ src0, const float* __restrict__ src1,
    const float* __restrict__ w, const float* __restrict__ bias,
    float* __restrict__ out)
{
    __shared__ __align__(16) u64 ws2[8][64];    // [cp][oc]
    __shared__ __align__(16) u64 xs2[8][128];   // [cp][px]

    const int n = blockIdx.y;
    const float* src = (n < 4) ? (src0 + (size_t)n * 128 * HWSZ)
                               : (src1 + (size_t)(n - 4) * 128 * HWSZ);
    const int px_base = blockIdx.x * 128;
    const int t = threadIdx.x;
    const int oc0 = (t >> 5) * 8;     // warp-uniform
    const int px0 = (t & 31) * 4;

    u64 acc[8][4];
    #pragma unroll
    for (int o = 0; o < 8; o++)
        #pragma unroll
        for (int p = 0; p < 4; p++) acc[o][p] = 0ull;

    for (int c0 = 0; c0 < 128; c0 += 16) {   // 8 c-pairs per stage
        __syncthreads();
        {   // weights: even/odd c contiguous in global -> direct u64 load
            int i = t;
            int cp = i >> 6, oc = i & 63;
            ws2[cp][oc] = *(const u64*)(w + oc * 128 + c0 + 2 * cp);
            i += 256; cp = i >> 6; oc = i & 63;
            ws2[cp][oc] = *(const u64*)(w + oc * 128 + c0 + 2 * cp);
        }
        #pragma unroll
        for (int it = 0; it < 4; it++) {      // 1024 x-entries
            int i = t + it * 256;
            int cp = i >> 7, px = i & 127;
            int gpx = px_base + px;
            u64 v = 0ull;
            if (gpx < HWSZ) {
                const float* p0 = src + (size_t)(c0 + 2 * cp) * HWSZ + gpx;
                v = pack2(p0[0], p0[HWSZ]);
            }
            xs2[cp][px] = v;
        }
        __syncthreads();

        #pragma unroll
        for (int cp = 0; cp < 8; cp++) {
            u64 wv[8], xv[4];
            #pragma unroll
            for (int i = 0; i < 4; i++) {
                ulonglong2 a = *(const ulonglong2*)&ws2[cp][oc0 + i * 2];
                wv[i * 2] = a.x; wv[i * 2 + 1] = a.y;
            }
            {
                ulonglong2 b0 = *(const ulonglong2*)&xs2[cp][px0];
                ulonglong2 b1 = *(const ulonglong2*)&xs2[cp][px0 + 2];
                xv[0] = b0.x; xv[1] = b0.y; xv[2] = b1.x; xv[3] = b1.y;
            }
            #pragma unroll
            for (int o = 0; o < 8; o++)
                #pragma unroll
                for (int p = 0; p < 4; p++)
                    ffma2(acc[o][p], wv[o], xv[p]);
        }
    }

    if (px_base + px0 < HWSZ) {
        #pragma unroll
        for (int o = 0; o < 8; o++) {
            float b = bias[oc0 + o];
            float2 l0 = unpack2(acc[o][0]), l1 = unpack2(acc[o][1]);
            float2 l2 = unpack2(acc[o][2]), l3 = unpack2(acc[o][3]);
            float4 r;
            r.x = fmaxf(l0.x + l0.y + b, 0.f);
            r.y = fmaxf(l1.x + l1.y + b, 0.f);
            r.z = fmaxf(l2.x + l2.y + b, 0.f);
            r.w = fmaxf(l3.x + l3.y + b, 0.f);
            *(float4*)&out[(size_t)(n * 64 + oc0 + o) * HWSZ + px_base + px0] = r;
        }
    }
}

// ============================================================================
// conv3x3 (64 -> CO) pad 1 + bias + relu, f32x2 over ic-pairs, LEAN registers.
// grid (13, 13, 8*CO/32), block 256. Tile 16x16 px x 32 oc.
// thread = 4 px (x-run) x 8 oc; acc = 32 u64. Warp-uniform ocg.
// ============================================================================
__global__ __launch_bounds__(256) void conv3x3_f2(
    const float* __restrict__ in, const float* __restrict__ w,
    const float* __restrict__ bias, float* __restrict__ out, int CO)
{
    __shared__ __align__(16) u64 si2[4][18][19];   // [icp][row][col] halo tile
    __shared__ __align__(16) u64 sw2[4][9][32];    // [icp][tap][oc]

    const int passes = CO >> 5;
    const int n = blockIdx.z / passes;
    const int pass = blockIdx.z - n * passes;
    const int ocbase = pass * 32;
    const int gy0 = blockIdx.y * 16, gx0 = blockIdx.x * 16;
    const int t = threadIdx.x;
    const int tx = t & 3, ty = (t >> 2) & 15, ocg = t >> 6;   // ocg warp-uniform
    const int oc0 = ocg * 8;
    const float* inb = in + (size_t)n * 64 * HWSZ;

    u64 acc[4][8];
    #pragma unroll
    for (int cc = 0; cc < 4; cc++)
        #pragma unroll
        for (int o = 0; o < 8; o++) acc[cc][o] = 0ull;

    for (int ic0 = 0; ic0 < 64; ic0 += 8) {   // 4 ic-pairs per stage
        __syncthreads();
        for (int i = t; i < 4 * 18 * 18; i += 256) {
            int icp = i / 324;
            int rem = i - icp * 324;
            int r = rem / 18, cc = rem - r * 18;
            int gy = gy0 - 1 + r, gx = gx0 - 1 + cc;
            u64 v = 0ull;
            if (gy >= 0 && gy < HD && gx >= 0 && gx < WD) {
                const float* p = inb + (size_t)(ic0 + 2 * icp) * HWSZ + gy * WD + gx;
                v = pack2(p[0], p[HWSZ]);
            }
            si2[icp][r][cc] = v;
        }
        for (int i = t; i < 4 * 9 * 32; i += 256) {
            int oc = i & 31;
            int rest = i >> 5;
            int icp = rest / 9, tap = rest - icp * 9;
            const float* p = w + (size_t)((ocbase + oc) * 64 + ic0 + 2 * icp) * 9 + tap;
            sw2[icp][tap][oc] = pack2(p[0], p[9]);
        }
        __syncthreads();

        #pragma unroll
        for (int icp = 0; icp < 4; icp++) {
            #pragma unroll
            for (int ki = 0; ki < 3; ki++) {
                u64 xw[6];
                #pragma unroll
                for (int c = 0; c < 6; c++)
                    xw[c] = si2[icp][ty + ki][tx * 4 + c];
                #pragma unroll
                for (int kj = 0; kj < 3; kj++) {
                    u64 wv[8];
                    #pragma unroll
                    for (int i2 = 0; i2 < 4; i2++) {
                        ulonglong2 a = *(const ulonglong2*)&sw2[icp][ki * 3 + kj][oc0 + i2 * 2];
                        wv[i2 * 2] = a.x; wv[i2 * 2 + 1] = a.y;
                    }
                    #pragma unroll
                    for (int cc = 0; cc < 4; cc++)
                        #pragma unroll
                        for (int o = 0; o < 8; o++)
                            ffma2(acc[cc][o], wv[o], xw[cc + kj]);
                }
            }
        }
    }

    const int gy = gy0 + ty;
    const int gx = gx0 + tx * 4;
    if (gy < HD && gx < WD) {
        #pragma unroll
        for (int o = 0; o < 8; o++) {
            float b = bias[ocbase + oc0 + o];
            float2 l0 = unpack2(acc[0][o]), l1 = unpack2(acc[1][o]);
            float2 l2 = unpack2(acc[2][o]), l3 = unpack2(acc[3][o]);
            float4 r;
            r.x = fmaxf(l0.x + l0.y + b, 0.f);
            r.y = fmaxf(l1.x + l1.y + b, 0.f);
            r.z = fmaxf(l2.x + l2.y + b, 0.f);
            r.w = fmaxf(l3.x + l3.y + b, 0.f);
            *(float4*)&out[(size_t)(n * CO + ocbase + oc0 + o) * HWSZ + gy * WD + gx] = r;
        }
    }
}

// ============================================================================
// correlation (R3 scalar, proven). grid (40, 9, 4), block 256.
// ============================================================================
__global__ __launch_bounds__(256) void corr_kernel(
    const float* __restrict__ e, float* __restrict__ corr)
{
    const int n = blockIdx.z, di = blockIdx.y;
    const int q = blockIdx.x * 256 + threadIdx.x;
    if (q >= 10000) return;
    const int p0 = q * 4;
    const int y = p0 / WD, x0 = p0 - y * WD;
    const float* sel = e + (size_t)n * 64 * HWSZ;
    const float* cur = e + (size_t)(n + 4) * 64 * HWSZ;

    float acc[9][4];
    #pragma unroll
    for (int dj = 0; dj < 9; dj++)
        #pragma unroll
        for (int j = 0; j < 4; j++) acc[dj][j] = 0.f;

    const int yy = y + di - 4;
    if (yy >= 0 && yy < HD) {
        #pragma unroll 1
        for (int c = 0; c < 64; c++) {
            float4 s = *(const float4*)&sel[(size_t)c * HWSZ + p0];
            const float* crow = &cur[(size_t)c * HWSZ + yy * WD];
            float win[12];
            #pragma unroll
            for (int i = 0; i < 12; i++) {
                int xx = x0 - 4 + i;
                win[i] = (xx >= 0 && xx < WD) ? crow[xx] : 0.f;
            }
            #pragma unroll
            for (int dj = 0; dj < 9; dj++) {
                acc[dj][0] += s.x * win[dj];
                acc[dj][1] += s.y * win[dj + 1];
                acc[dj][2] += s.z * win[dj + 2];
                acc[dj][3] += s.w * win[dj + 3];
            }
        }
    }
    #pragma unroll
    for (int dj = 0; dj < 9; dj++) {
        float4 r = {acc[dj][0], acc[dj][1], acc[dj][2], acc[dj][3]};
        *(float4*)&corr[(size_t)(n * 81 + di * 9 + dj) * HWSZ + p0] = r;
    }
}

// ============================================================================
// softmax over k=81, online (R5-proven). grid 157, block 256.
// ============================================================================
__global__ __launch_bounds__(256) void softmax81(float* __restrict__ c)
{
    const int tid = blockIdx.x * 256 + threadIdx.x;
    if (tid >= 40000) return;
    const int n = tid / 10000, q = tid - n * 10000;
    float* base = c + (size_t)n * 81 * HWSZ + q * 4;

    float4 m = {-1e30f, -1e30f, -1e30f, -1e30f};
    float4 s = {0.f, 0.f, 0.f, 0.f};
    for (int k = 0; k < 81; k++) {
        float4 v = *(const float4*)(base + (size_t)k * HWSZ);
        float4 nm;
        nm.x = fmaxf(m.x, v.x); nm.y = fmaxf(m.y, v.y);
        nm.z = fmaxf(m.z, v.z); nm.w = fmaxf(m.w, v.w);
        s.x = s.x * __expf(m.x - nm.x) + __expf(v.x - nm.x);
        s.y = s.y * __expf(m.y - nm.y) + __expf(v.y - nm.y);
        s.z = s.z * __expf(m.z - nm.z) + __expf(v.z - nm.z);
        s.w = s.w * __expf(m.w - nm.w) + __expf(v.w - nm.w);
        m = nm;
    }
    float4 inv = {1.f / s.x, 1.f / s.y, 1.f / s.z, 1.f / s.w};
    for (int k = 0; k < 81; k++) {
        float* p = base + (size_t)k * HWSZ;
        float4 v = *(const float4*)p;
        float4 r;
        r.x = __expf(v.x - m.x) * inv.x;
        r.y = __expf(v.y - m.y) * inv.y;
        r.z = __expf(v.z - m.z) * inv.z;
        r.w = __expf(v.w - m.w) * inv.w;
        *(float4*)p = r;
    }
}

// ============================================================================
// align (R3 scalar, proven). grid (157, 4, 4), block 256.
// ============================================================================
__global__ __launch_bounds__(256) void align_kernel(
    const float* __restrict__ wgt, const float* __restrict__ fsel,
    float* __restrict__ outp)
{
    __shared__ __align__(16) float ws[9 * 256];

    const int n = blockIdx.z, cpass = blockIdx.y;
    const int t = threadIdx.x;
    const int ql = t & 63, cg = t >> 6;
    const int qb = blockIdx.x * 64;
    const int q = qb + ql;
    const bool active = q < 10000;
    const int p0 = q * 4;
    const int y = p0 / WD, x0 = p0 - y * WD;
    const int c0 = cpass * 32 + cg * 8;
    const float* sel = fsel + (size_t)n * 128 * HWSZ;
    const int pxbase = qb * 4;

    float acc[8][4];
    #pragma unroll
    for (int ci = 0; ci < 8; ci++)
        #pragma unroll
        for (int j = 0; j < 4; j++) acc[ci][j] = 0.f;

    for (int di = 0; di < 9; di++) {
        __syncthreads();
        #pragma unroll
        for (int i2 = 0; i2 < 9; i2++) {
            int i = t + i2 * 256;
            int dj = i >> 8, col = i & 255;
            int idx = pxbase + col;
            ws[i] = (idx < HWSZ) ? wgt[(size_t)(n * 81 + di * 9 + dj) * HWSZ + idx] : 0.f;
        }
        __syncthreads();

        const int yy = y + di - 4;
        if (active && yy >= 0 && yy < HD) {
            float4 wv[9];
            #pragma unroll
            for (int dj = 0; dj < 9; dj++)
                wv[dj] = *(const float4*)&ws[dj * 256 + ql * 4];
            #pragma unroll
            for (int ci = 0; ci < 8; ci++) {
                const float* srow = sel + (size_t)(c0 + ci) * HWSZ + yy * WD;
                float win[12];
                #pragma unroll
                for (int i2 = 0; i2 < 12; i2++) {
                    int xx = x0 - 4 + i2;
                    win[i2] = (xx >= 0 && xx < WD) ? srow[xx] : 0.f;
                }
                #pragma unroll
                for (int dj = 0; dj < 9; dj++) {
                    acc[ci][0] += wv[dj].x * win[dj];
                    acc[ci][1] += wv[dj].y * win[dj + 1];
                    acc[ci][2] += wv[dj].z * win[dj + 2];
                    acc[ci][3] += wv[dj].w * win[dj + 3];
                }
            }
        }
    }

    if (active) {
        #pragma unroll
        for (int ci = 0; ci < 8; ci++) {
            float4 r = {acc[ci][0], acc[ci][1], acc[ci][2], acc[ci][3]};
            *(float4*)&outp[(size_t)(n * 128 + c0 + ci) * HWSZ + p0] = r;
        }
    }
}

// ============================================================================
// ag3 1x1 (32->1) + relu, 2-way softmax, final blend (R3 proven).
// ============================================================================
__global__ __launch_bounds__(256) void final_blend(
    const float* __restrict__ a2, const float* __restrict__ alg,
    const float* __restrict__ fcur, const float* __restrict__ w3,
    const float* __restrict__ b3, float* __restrict__ out)
{
    const int tid = blockIdx.x * 256 + threadIdx.x;
    if (tid >= 40000) return;
    const int n = tid / 10000, q = tid - n * 10000;
    const int p0 = q * 4;

    float4 z0 = {0.f, 0.f, 0.f, 0.f}, z1 = {0.f, 0.f, 0.f, 0.f};
    #pragma unroll 4
    for (int c = 0; c < 32; c++) {
        float wc = w3[c];
        float4 va = *(const float4*)&a2[(size_t)(n * 32 + c) * HWSZ + p0];
        float4 vb = *(const float4*)&a2[(size_t)((n + 4) * 32 + c) * HWSZ + p0];
        z0.x += wc * va.x; z0.y += wc * va.y; z0.z += wc * va.z; z0.w += wc * va.w;
        z1.x += wc * vb.x; z1.y += wc * vb.y; z1.z += wc * vb.z; z1.w += wc * vb.w;
    }
    const float b = b3[0];
    z0.x = fmaxf(z0.x + b, 0.f); z0.y = fmaxf(z0.y + b, 0.f);
    z0.z = fmaxf(z0.z + b, 0.f); z0.w = fmaxf(z0.w + b, 0.f);
    z1.x = fmaxf(z1.x + b, 0.f); z1.y = fmaxf(z1.y + b, 0.f);
    z1.z = fmaxf(z1.z + b, 0.f); z1.w = fmaxf(z1.w + b, 0.f);

    float4 w0;
    w0.x = 1.f / (1.f + __expf(z1.x - z0.x));
    w0.y = 1.f / (1.f + __expf(z1.y - z0.y));
    w0.z = 1.f / (1.f + __expf(z1.z - z0.z));
    w0.w = 1.f / (1.f + __expf(z1.w - z0.w));

    #pragma unroll 4
    for (int c = 0; c < 128; c++) {
        float4 va = *(const float4*)&alg[(size_t)(n * 128 + c) * HWSZ + p0];
        float4 vc = *(const float4*)&fcur[(size_t)(n * 128 + c) * HWSZ + p0];
        float4 r;
        r.x = w0.x * va.x + (1.f - w0.x) * vc.x;
        r.y = w0.y * va.y + (1.f - w0.y) * vc.y;
        r.z = w0.z * va.z + (1.f - w0.z) * vc.z;
        r.w = w0.w * va.w + (1.f - w0.w) * vc.w;
        *(float4*)&out[(size_t)(n * 128 + c) * HWSZ + p0] = r;
    }
}

// ============================================================================
extern "C" void kernel_launch(void* const* d_in, const int* in_sizes, int n_in,
                              void* d_out, int out_size)
{
    (void)in_sizes; (void)n_in; (void)out_size;
    const float* fsel  = (const float*)d_in[0];
    const float* fcur  = (const float*)d_in[1];
    const float* ec1_w = (const float*)d_in[2];
    const float* ec1_b = (const float*)d_in[3];
    const float* ec2_w = (const float*)d_in[4];
    const float* ec2_b = (const float*)d_in[5];
    const float* ag1_w = (const float*)d_in[6];
    const float* ag1_b = (const float*)d_in[7];
    const float* ag2_w = (const float*)d_in[8];
    const float* ag2_b = (const float*)d_in[9];
    const float* ag3_w = (const float*)d_in[10];
    const float* ag3_b = (const float*)d_in[11];
    float* out = (float*)d_out;

    float *pe, *pe2, *pcorr, *palign;
    cudaGetSymbolAddress((void**)&pe,     g_e);
    cudaGetSymbolAddress((void**)&pe2,    g_e2);
    cudaGetSymbolAddress((void**)&pcorr,  g_corr);
    cudaGetSymbolAddress((void**)&palign, g_align);

    conv1x1_f2<<<dim3(313, 8), 256>>>(fsel, fcur, ec1_w, ec1_b, pe);
    conv3x3_f2<<<dim3(13, 13, 16), 256>>>(pe, ec2_w, ec2_b, pe2, 64);
    corr_kernel<<<dim3(40, 9, 4), 256>>>(pe2, pcorr);
    softmax81<<<157, 256>>>(pcorr);
    align_kernel<<<dim3(157, 4, 4), 256>>>(pcorr, fsel, palign);
    conv1x1_f2<<<dim3(313, 8), 256>>>(palign, fcur, ag1_w, ag1_b, pe);
    conv3x3_f2<<<dim3(13, 13, 8), 256>>>(pe, ag2_w, ag2_b, pe2, 32);
    final_blend<<<157, 256>>>(pe2, palign, fcur, ag3_w, ag3_b, out);
}

// round 14
// speedup vs baseline: 1.1924x; 1.0288x over previous
#include <cuda_runtime.h>
#include <cstdint>

#define HWSZ 40000
#define WD 200
#define HD 200

typedef unsigned long long u64;

__device__ __forceinline__ u64 pack2(float lo, float hi) {
    u64 r; asm("mov.b64 %0, {%1, %2};" : "=l"(r) : "f"(lo), "f"(hi)); return r;
}
__device__ __forceinline__ void ffma2(u64 &d, u64 a, u64 b) {
    asm("fma.rn.f32x2 %0, %1, %2, %0;" : "+l"(d) : "l"(a), "l"(b));
}
__device__ __forceinline__ float2 unpack2(u64 v) {
    float2 r; asm("mov.b64 {%0, %1}, %2;" : "=f"(r.x), "=f"(r.y) : "l"(v)); return r;
}

// ---- scratch (allocation-free: __device__ globals) ----
__device__ float g_e    [8 * 64  * HWSZ];
__device__ float g_e2   [8 * 64  * HWSZ];
__device__ float g_corr [4 * 81  * HWSZ];
__device__ float g_align[4 * 128 * HWSZ];
__device__ float g_Uw   [16 * 64 * 64];   // Winograd-transformed weights [pos][ic][oc]

// ============================================================================
// conv1x1 (128 -> 64) + bias + relu, f32x2 over c-pairs (R13 proven).
// ============================================================================
__global__ __launch_bounds__(256) void conv1x1_f2(
    const float* __restrict__ src0, const float* __restrict__ src1,
    const float* __restrict__ w, const float* __restrict__ bias,
    float* __restrict__ out)
{
    __shared__ __align__(16) u64 ws2[8][64];
    __shared__ __align__(16) u64 xs2[8][128];

    const int n = blockIdx.y;
    const float* src = (n < 4) ? (src0 + (size_t)n * 128 * HWSZ)
                               : (src1 + (size_t)(n - 4) * 128 * HWSZ);
    const int px_base = blockIdx.x * 128;
    const int t = threadIdx.x;
    const int oc0 = (t >> 5) * 8;
    const int px0 = (t & 31) * 4;

    u64 acc[8][4];
    #pragma unroll
    for (int o = 0; o < 8; o++)
        #pragma unroll
        for (int p = 0; p < 4; p++) acc[o][p] = 0ull;

    for (int c0 = 0; c0 < 128; c0 += 16) {
        __syncthreads();
        {
            int i = t;
            int cp = i >> 6, oc = i & 63;
            ws2[cp][oc] = *(const u64*)(w + oc * 128 + c0 + 2 * cp);
            i += 256; cp = i >> 6; oc = i & 63;
            ws2[cp][oc] = *(const u64*)(w + oc * 128 + c0 + 2 * cp);
        }
        #pragma unroll
        for (int it = 0; it < 4; it++) {
            int i = t + it * 256;
            int cp = i >> 7, px = i & 127;
            int gpx = px_base + px;
            u64 v = 0ull;
            if (gpx < HWSZ) {
                const float* p0 = src + (size_t)(c0 + 2 * cp) * HWSZ + gpx;
                v = pack2(p0[0], p0[HWSZ]);
            }
            xs2[cp][px] = v;
        }
        __syncthreads();

        #pragma unroll
        for (int cp = 0; cp < 8; cp++) {
            u64 wv[8], xv[4];
            #pragma unroll
            for (int i = 0; i < 4; i++) {
                ulonglong2 a = *(const ulonglong2*)&ws2[cp][oc0 + i * 2];
                wv[i * 2] = a.x; wv[i * 2 + 1] = a.y;
            }
            {
                ulonglong2 b0 = *(const ulonglong2*)&xs2[cp][px0];
                ulonglong2 b1 = *(const ulonglong2*)&xs2[cp][px0 + 2];
                xv[0] = b0.x; xv[1] = b0.y; xv[2] = b1.x; xv[3] = b1.y;
            }
            #pragma unroll
            for (int o = 0; o < 8; o++)
                #pragma unroll
                for (int p = 0; p < 4; p++)
                    ffma2(acc[o][p], wv[o], xv[p]);
        }
    }

    if (px_base + px0 < HWSZ) {
        #pragma unroll
        for (int o = 0; o < 8; o++) {
            float b = bias[oc0 + o];
            float2 l0 = unpack2(acc[o][0]), l1 = unpack2(acc[o][1]);
            float2 l2 = unpack2(acc[o][2]), l3 = unpack2(acc[o][3]);
            float4 r;
            r.x = fmaxf(l0.x + l0.y + b, 0.f);
            r.y = fmaxf(l1.x + l1.y + b, 0.f);
            r.z = fmaxf(l2.x + l2.y + b, 0.f);
            r.w = fmaxf(l3.x + l3.y + b, 0.f);
            *(float4*)&out[(size_t)(n * 64 + oc0 + o) * HWSZ + px_base + px0] = r;
        }
    }
}

// ============================================================================
// Winograd U prep: w[oc][ic][3][3] -> U = G g G^T, stored Ug[pos][ic][oc]
// ============================================================================
__global__ void wino_uprep(const float* __restrict__ w, float* __restrict__ Ug, int CO)
{
    int i = blockIdx.x * 256 + threadIdx.x;
    if (i >= CO * 64) return;
    int oc = i >> 6, ic = i & 63;
    const float* g = w + (size_t)(oc * 64 + ic) * 9;
    float g0[3] = {g[0], g[1], g[2]};
    float g1[3] = {g[3], g[4], g[5]};
    float g2[3] = {g[6], g[7], g[8]};
    float x[4][3];
    #pragma unroll
    for (int j = 0; j < 3; j++) {
        x[0][j] = g0[j];
        x[1][j] = 0.5f * (g0[j] + g1[j] + g2[j]);
        x[2][j] = 0.5f * (g0[j] - g1[j] + g2[j]);
        x[3][j] = g2[j];
    }
    #pragma unroll
    for (int r = 0; r < 4; r++) {
        float u0 = x[r][0];
        float u1 = 0.5f * (x[r][0] + x[r][1] + x[r][2]);
        float u2 = 0.5f * (x[r][0] - x[r][1] + x[r][2]);
        float u3 = x[r][2];
        Ug[(size_t)(r * 4 + 0) * 64 * CO + ic * CO + oc] = u0;
        Ug[(size_t)(r * 4 + 1) * 64 * CO + ic * CO + oc] = u1;
        Ug[(size_t)(r * 4 + 2) * 64 * CO + ic * CO + oc] = u2;
        Ug[(size_t)(r * 4 + 3) * 64 * CO + ic * CO + oc] = u3;
    }
}

// ============================================================================
// Winograd F(2x2,3x3) conv3x3 (64 -> CO) pad 1 + bias + relu.
// grid (625, 8), block 256 = 16 pos x 16 tiles. Patch = 4x4 tiles = 8x8 px.
// smem: sIn[16ic][10][12] | sV[16pos][16ic][16tile] | sU[16pos][16ic][CO/2] u64
// ============================================================================
template<int CO>
__global__ __launch_bounds__(256) void conv3x3_wino(
    const float* __restrict__ in, const float* __restrict__ Ug,
    const float* __restrict__ bias, float* __restrict__ out)
{
    extern __shared__ float sm[];
    float* sIn = sm;                               // 16*120 = 1920 floats
    float* sV  = sm + 1920;                        // 16*16*16 = 4096 floats
    u64*   sU  = (u64*)(sm + 1920 + 4096);         // 16*16*(CO/2) u64

    const int n = blockIdx.y;
    const int patch = blockIdx.x;
    const int py = patch / 25, pxp = patch - py * 25;
    const int gy0 = py * 8, gx0 = pxp * 8;
    const float* inb = in + (size_t)n * 64 * HWSZ;
    const int t = threadIdx.x;
    const int tile = t & 15, pos = t >> 4;         // GEMM mapping

    u64 acc[CO / 2];
    #pragma unroll
    for (int op = 0; op < CO / 2; op++) acc[op] = 0ull;

    for (int ic0 = 0; ic0 < 64; ic0 += 16) {
        __syncthreads();
        // ---- fill input patch 16ic x 10 x 10 (halo, zero-pad) ----
        for (int i = t; i < 1600; i += 256) {
            int ic = i / 100;
            int rem = i - ic * 100;
            int r = rem / 10, c = rem - r * 10;
            int gy = gy0 - 1 + r, gx = gx0 - 1 + c;
            float v = 0.f;
            if (gy >= 0 && gy < HD && gx >= 0 && gx < WD)
                v = inb[(size_t)(ic0 + ic) * HWSZ + gy * WD + gx];
            sIn[ic * 120 + r * 12 + c] = v;
        }
        // ---- fill U chunk [16pos][16ic][CO/2] u64 (coalesced) ----
        for (int i = t; i < 16 * 16 * (CO / 2); i += 256) {
            int op = i & (CO / 2 - 1);
            int rest = i / (CO / 2);
            int ic = rest & 15, p = rest >> 4;
            sU[i] = *(const u64*)(Ug + (size_t)p * 64 * CO + (ic0 + ic) * CO + 2 * op);
        }
        __syncthreads();
        // ---- V = B^T d B : thread = (icT, tileT), 256 active ----
        {
            const int icT = t >> 4, tileT = t & 15;
            const int tr = tileT >> 2, tc = tileT & 3;
            const float* dp = sIn + icT * 120 + tr * 2 * 12 + tc * 2;
            float d[4][4];
            #pragma unroll
            for (int i = 0; i < 4; i++)
                #pragma unroll
                for (int j = 0; j < 4; j++) d[i][j] = dp[i * 12 + j];
            float r[4][4];
            #pragma unroll
            for (int j = 0; j < 4; j++) {
                r[0][j] = d[0][j] - d[2][j];
                r[1][j] = d[1][j] + d[2][j];
                r[2][j] = d[2][j] - d[1][j];
                r[3][j] = d[1][j] - d[3][j];
            }
            #pragma unroll
            for (int i = 0; i < 4; i++) {
                float v0 = r[i][0] - r[i][2];
                float v1 = r[i][1] + r[i][2];
                float v2 = r[i][2] - r[i][1];
                float v3 = r[i][1] - r[i][3];
                sV[(i * 4 + 0) * 256 + icT * 16 + tileT] = v0;
                sV[(i * 4 + 1) * 256 + icT * 16 + tileT] = v1;
                sV[(i * 4 + 2) * 256 + icT * 16 + tileT] = v2;
                sV[(i * 4 + 3) * 256 + icT * 16 + tileT] = v3;
            }
        }
        __syncthreads();
        // ---- Hadamard-GEMM: acc[oc] += U[pos][ic][oc] * V[pos][ic][tile] ----
        {
            const float* vp = sV + pos * 256 + tile;
            const u64* up = sU + pos * 16 * (CO / 2);
            #pragma unroll 2
            for (int ic = 0; ic < 16; ic++) {
                float v = vp[ic * 16];
                u64 vv = pack2(v, v);
                const u64* u = up + ic * (CO / 2);
                #pragma unroll
                for (int op = 0; op < CO / 2; op += 2) {
                    ulonglong2 uu = *(const ulonglong2*)(u + op);
                    ffma2(acc[op], vv, uu.x);
                    ffma2(acc[op + 1], vv, uu.y);
                }
            }
        }
    }

    // ---- output transform: Y = A^T M A, oc chunks of 16 via smem transpose ----
    float* Mx = sV;   // 16pos x 16tile x 16oc = 4096 floats
    const int ocl = t & 15, tX = t >> 4;   // transform mapping (linear smem reads)
    #pragma unroll
    for (int chunk = 0; chunk < CO / 16; chunk++) {
        __syncthreads();
        {   // write this thread's (pos,tile) slice of 16 oc
            float* wp = Mx + pos * 256 + tile * 16;
            #pragma unroll
            for (int op2 = 0; op2 < 8; op2++) {
                float2 f = unpack2(acc[chunk * 8 + op2]);
                wp[op2 * 2] = f.x; wp[op2 * 2 + 1] = f.y;
            }
        }
        __syncthreads();
        {   // read 16 positions for (tX, ocl), transform, store 2x2 px
            float m[4][4];
            #pragma unroll
            for (int p = 0; p < 16; p++)
                m[p >> 2][p & 3] = Mx[p * 256 + tX * 16 + ocl];
            float a0[4], a1[4];
            #pragma unroll
            for (int j = 0; j < 4; j++) {
                a0[j] = m[0][j] + m[1][j] + m[2][j];
                a1[j] = m[1][j] - m[2][j] - m[3][j];
            }
            float y00 = a0[0] + a0[1] + a0[2];
            float y01 = a0[1] - a0[2] - a0[3];
            float y10 = a1[0] + a1[1] + a1[2];
            float y11 = a1[1] - a1[2] - a1[3];
            int oc = chunk * 16 + ocl;
            float b = __ldg(bias + oc);
            int gy = gy0 + (tX >> 2) * 2;
            int gx = gx0 + (tX & 3) * 2;
            float* op_ = out + (size_t)(n * CO + oc) * HWSZ + gy * WD + gx;
            op_[0]      = fmaxf(y00 + b, 0.f);
            op_[1]      = fmaxf(y01 + b, 0.f);
            op_[WD]     = fmaxf(y10 + b, 0.f);
            op_[WD + 1] = fmaxf(y11 + b, 0.f);
        }
    }
}

// ============================================================================
// correlation (proven). grid (40, 9, 4), block 256.
// ============================================================================
__global__ __launch_bounds__(256) void corr_kernel(
    const float* __restrict__ e, float* __restrict__ corr)
{
    const int n = blockIdx.z, di = blockIdx.y;
    const int q = blockIdx.x * 256 + threadIdx.x;
    if (q >= 10000) return;
    const int p0 = q * 4;
    const int y = p0 / WD, x0 = p0 - y * WD;
    const float* sel = e + (size_t)n * 64 * HWSZ;
    const float* cur = e + (size_t)(n + 4) * 64 * HWSZ;

    float acc[9][4];
    #pragma unroll
    for (int dj = 0; dj < 9; dj++)
        #pragma unroll
        for (int j = 0; j < 4; j++) acc[dj][j] = 0.f;

    const int yy = y + di - 4;
    if (yy >= 0 && yy < HD) {
        #pragma unroll 1
        for (int c = 0; c < 64; c++) {
            float4 s = *(const float4*)&sel[(size_t)c * HWSZ + p0];
            const float* crow = &cur[(size_t)c * HWSZ + yy * WD];
            float win[12];
            #pragma unroll
            for (int i = 0; i < 12; i++) {
                int xx = x0 - 4 + i;
                win[i] = (xx >= 0 && xx < WD) ? crow[xx] : 0.f;
            }
            #pragma unroll
            for (int dj = 0; dj < 9; dj++) {
                acc[dj][0] += s.x * win[dj];
                acc[dj][1] += s.y * win[dj + 1];
                acc[dj][2] += s.z * win[dj + 2];
                acc[dj][3] += s.w * win[dj + 3];
            }
        }
    }
    #pragma unroll
    for (int dj = 0; dj < 9; dj++) {
        float4 r = {acc[dj][0], acc[dj][1], acc[dj][2], acc[dj][3]};
        *(float4*)&corr[(size_t)(n * 81 + di * 9 + dj) * HWSZ + p0] = r;
    }
}

// ============================================================================
// softmax over k=81, online (proven). grid 157, block 256.
// ============================================================================
__global__ __launch_bounds__(256) void softmax81(float* __restrict__ c)
{
    const int tid = blockIdx.x * 256 + threadIdx.x;
    if (tid >= 40000) return;
    const int n = tid / 10000, q = tid - n * 10000;
    float* base = c + (size_t)n * 81 * HWSZ + q * 4;

    float4 m = {-1e30f, -1e30f, -1e30f, -1e30f};
    float4 s = {0.f, 0.f, 0.f, 0.f};
    for (int k = 0; k < 81; k++) {
        float4 v = *(const float4*)(base + (size_t)k * HWSZ);
        float4 nm;
        nm.x = fmaxf(m.x, v.x); nm.y = fmaxf(m.y, v.y);
        nm.z = fmaxf(m.z, v.z); nm.w = fmaxf(m.w, v.w);
        s.x = s.x * __expf(m.x - nm.x) + __expf(v.x - nm.x);
        s.y = s.y * __expf(m.y - nm.y) + __expf(v.y - nm.y);
        s.z = s.z * __expf(m.z - nm.z) + __expf(v.z - nm.z);
        s.w = s.w * __expf(m.w - nm.w) + __expf(v.w - nm.w);
        m = nm;
    }
    float4 inv = {1.f / s.x, 1.f / s.y, 1.f / s.z, 1.f / s.w};
    for (int k = 0; k < 81; k++) {
        float* p = base + (size_t)k * HWSZ;
        float4 v = *(const float4*)p;
        float4 r;
        r.x = __expf(v.x - m.x) * inv.x;
        r.y = __expf(v.y - m.y) * inv.y;
        r.z = __expf(v.z - m.z) * inv.z;
        r.w = __expf(v.w - m.w) * inv.w;
        *(float4*)p = r;
    }
}

// ============================================================================
// align (proven). grid (157, 4, 4), block 256.
// ============================================================================
__global__ __launch_bounds__(256) void align_kernel(
    const float* __restrict__ wgt, const float* __restrict__ fsel,
    float* __restrict__ outp)
{
    __shared__ __align__(16) float ws[9 * 256];

    const int n = blockIdx.z, cpass = blockIdx.y;
    const int t = threadIdx.x;
    const int ql = t & 63, cg = t >> 6;
    const int qb = blockIdx.x * 64;
    const int q = qb + ql;
    const bool active = q < 10000;
    const int p0 = q * 4;
    const int y = p0 / WD, x0 = p0 - y * WD;
    const int c0 = cpass * 32 + cg * 8;
    const float* sel = fsel + (size_t)n * 128 * HWSZ;
    const int pxbase = qb * 4;

    float acc[8][4];
    #pragma unroll
    for (int ci = 0; ci < 8; ci++)
        #pragma unroll
        for (int j = 0; j < 4; j++) acc[ci][j] = 0.f;

    for (int di = 0; di < 9; di++) {
        __syncthreads();
        #pragma unroll
        for (int i2 = 0; i2 < 9; i2++) {
            int i = t + i2 * 256;
            int dj = i >> 8, col = i & 255;
            int idx = pxbase + col;
            ws[i] = (idx < HWSZ) ? wgt[(size_t)(n * 81 + di * 9 + dj) * HWSZ + idx] : 0.f;
        }
        __syncthreads();

        const int yy = y + di - 4;
        if (active && yy >= 0 && yy < HD) {
            float4 wv[9];
            #pragma unroll
            for (int dj = 0; dj < 9; dj++)
                wv[dj] = *(const float4*)&ws[dj * 256 + ql * 4];
            #pragma unroll
            for (int ci = 0; ci < 8; ci++) {
                const float* srow = sel + (size_t)(c0 + ci) * HWSZ + yy * WD;
                float win[12];
                #pragma unroll
                for (int i2 = 0; i2 < 12; i2++) {
                    int xx = x0 - 4 + i2;
                    win[i2] = (xx >= 0 && xx < WD) ? srow[xx] : 0.f;
                }
                #pragma unroll
                for (int dj = 0; dj < 9; dj++) {
                    acc[ci][0] += wv[dj].x * win[dj];
                    acc[ci][1] += wv[dj].y * win[dj + 1];
                    acc[ci][2] += wv[dj].z * win[dj + 2];
                    acc[ci][3] += wv[dj].w * win[dj + 3];
                }
            }
        }
    }

    if (active) {
        #pragma unroll
        for (int ci = 0; ci < 8; ci++) {
            float4 r = {acc[ci][0], acc[ci][1], acc[ci][2], acc[ci][3]};
            *(float4*)&outp[(size_t)(n * 128 + c0 + ci) * HWSZ + p0] = r;
        }
    }
}

// ============================================================================
// ag3 1x1 (32->1) + relu, 2-way softmax, final blend (proven).
// ============================================================================
__global__ __launch_bounds__(256) void final_blend(
    const float* __restrict__ a2, const float* __restrict__ alg,
    const float* __restrict__ fcur, const float* __restrict__ w3,
    const float* __restrict__ b3, float* __restrict__ out)
{
    const int tid = blockIdx.x * 256 + threadIdx.x;
    if (tid >= 40000) return;
    const int n = tid / 10000, q = tid - n * 10000;
    const int p0 = q * 4;

    float4 z0 = {0.f, 0.f, 0.f, 0.f}, z1 = {0.f, 0.f, 0.f, 0.f};
    #pragma unroll 4
    for (int c = 0; c < 32; c++) {
        float wc = w3[c];
        float4 va = *(const float4*)&a2[(size_t)(n * 32 + c) * HWSZ + p0];
        float4 vb = *(const float4*)&a2[(size_t)((n + 4) * 32 + c) * HWSZ + p0];
        z0.x += wc * va.x; z0.y += wc * va.y; z0.z += wc * va.z; z0.w += wc * va.w;
        z1.x += wc * vb.x; z1.y += wc * vb.y; z1.z += wc * vb.z; z1.w += wc * vb.w;
    }
    const float b = b3[0];
    z0.x = fmaxf(z0.x + b, 0.f); z0.y = fmaxf(z0.y + b, 0.f);
    z0.z = fmaxf(z0.z + b, 0.f); z0.w = fmaxf(z0.w + b, 0.f);
    z1.x = fmaxf(z1.x + b, 0.f); z1.y = fmaxf(z1.y + b, 0.f);
    z1.z = fmaxf(z1.z + b, 0.f); z1.w = fmaxf(z1.w + b, 0.f);

    float4 w0;
    w0.x = 1.f / (1.f + __expf(z1.x - z0.x));
    w0.y = 1.f / (1.f + __expf(z1.y - z0.y));
    w0.z = 1.f / (1.f + __expf(z1.z - z0.z));
    w0.w = 1.f / (1.f + __expf(z1.w - z0.w));

    #pragma unroll 4
    for (int c = 0; c < 128; c++) {
        float4 va = *(const float4*)&alg[(size_t)(n * 128 + c) * HWSZ + p0];
        float4 vc = *(const float4*)&fcur[(size_t)(n * 128 + c) * HWSZ + p0];
        float4 r;
        r.x = w0.x * va.x + (1.f - w0.x) * vc.x;
        r.y = w0.y * va.y + (1.f - w0.y) * vc.y;
        r.z = w0.z * va.z + (1.f - w0.z) * vc.z;
        r.w = w0.w * va.w + (1.f - w0.w) * vc.w;
        *(float4*)&out[(size_t)(n * 128 + c) * HWSZ + p0] = r;
    }
}

// ============================================================================
extern "C" void kernel_launch(void* const* d_in, const int* in_sizes, int n_in,
                              void* d_out, int out_size)
{
    (void)in_sizes; (void)n_in; (void)out_size;
    const float* fsel  = (const float*)d_in[0];
    const float* fcur  = (const float*)d_in[1];
    const float* ec1_w = (const float*)d_in[2];
    const float* ec1_b = (const float*)d_in[3];
    const float* ec2_w = (const float*)d_in[4];
    const float* ec2_b = (const float*)d_in[5];
    const float* ag1_w = (const float*)d_in[6];
    const float* ag1_b = (const float*)d_in[7];
    const float* ag2_w = (const float*)d_in[8];
    const float* ag2_b = (const float*)d_in[9];
    const float* ag3_w = (const float*)d_in[10];
    const float* ag3_b = (const float*)d_in[11];
    float* out = (float*)d_out;

    float *pe, *pe2, *pcorr, *palign, *pU;
    cudaGetSymbolAddress((void**)&pe,     g_e);
    cudaGetSymbolAddress((void**)&pe2,    g_e2);
    cudaGetSymbolAddress((void**)&pcorr,  g_corr);
    cudaGetSymbolAddress((void**)&palign, g_align);
    cudaGetSymbolAddress((void**)&pU,     g_Uw);

    // smem: 1920 + 4096 floats + 16*16*(CO/2) u64
    const int smem64 = (1920 + 4096) * 4 + 16 * 16 * 32 * 8;   // 89600
    const int smem32 = (1920 + 4096) * 4 + 16 * 16 * 16 * 8;   // 56832
    cudaFuncSetAttribute(conv3x3_wino<64>, cudaFuncAttributeMaxDynamicSharedMemorySize, smem64);
    cudaFuncSetAttribute(conv3x3_wino<32>, cudaFuncAttributeMaxDynamicSharedMemorySize, smem32);

    // encoder branch
    conv1x1_f2<<<dim3(313, 8), 256>>>(fsel, fcur, ec1_w, ec1_b, pe);
    wino_uprep<<<16, 256>>>(ec2_w, pU, 64);
    conv3x3_wino<64><<<dim3(625, 8), 256, smem64>>>(pe, pU, ec2_b, pe2);
    // correlation + softmax + align
    corr_kernel<<<dim3(40, 9, 4), 256>>>(pe2, pcorr);
    softmax81<<<157, 256>>>(pcorr);
    align_kernel<<<dim3(157, 4, 4), 256>>>(pcorr, fsel, palign);
    // aggregation branch
    conv1x1_f2<<<dim3(313, 8), 256>>>(palign, fcur, ag1_w, ag1_b, pe);
    wino_uprep<<<8, 256>>>(ag2_w, pU, 32);
    conv3x3_wino<32><<<dim3(625, 8), 256, smem32>>>(pe, pU, ag2_b, pe2);
    final_blend<<<157, 256>>>(pe2, palign, fcur, ag3_w, ag3_b, out);
}